// round 16
// baseline (speedup 1.0000x reference)
#include <cuda_runtime.h>

#define DIM     512
#define D_INNER 1024
#define DT_RANK 32
#define D_STATE 16
#define B_SZ    4
#define N_TOK   4097

// ---------------- scratch (device globals, allocation-free) ----------------
__device__ __align__(16) float g_q    [B_SZ * DIM];
__device__ __align__(16) float g_xs   [B_SZ * D_INNER];
__device__ __align__(16) float g_sz   [B_SZ * D_INNER];
__device__ __align__(16) float g_y    [B_SZ * D_INNER];
__device__ __align__(16) float g_mixed[B_SZ * DIM];

// ---------------- helpers ----------------
__device__ __forceinline__ float siluf(float x) { return x / (1.0f + __expf(-x)); }
__device__ __forceinline__ float softplusf(float x) {
    return (x > 20.0f) ? x : log1pf(__expf(x));
}
__device__ __forceinline__ void pf_l2(const float* p) {
    asm volatile("prefetch.global.L2 [%0];" :: "l"(p));
}

// Warp-collective dot of two length-(N4*4) float vectors (float4 reads).
template <int N4>
__device__ __forceinline__ float warp_dot(const float4* __restrict__ v4,
                                          const float4* __restrict__ w4) {
    int lane = threadIdx.x & 31;
    float s = 0.0f;
#pragma unroll
    for (int i = 0; i < N4 / 32; i++) {
        float4 a = v4[lane + i * 32];
        float4 b = w4[lane + i * 32];
        s += a.x * b.x + a.y * b.y + a.z * b.z + a.w * b.w;
    }
#pragma unroll
    for (int off = 16; off; off >>= 1)
        s += __shfl_xor_sync(0xffffffffu, s, off);
    return s;
}

// ============ K0: bulk patch copy — MANY TINY BLOCKS (dispatch-friendly) ====
// 8192 blocks x 256 thr x 1 float4 = 2,097,152 float4. Small blocks retire
// quickly, constantly freeing SM slots that high-priority chain blocks take.
__global__ void __launch_bounds__(256) k_copy(const float4* __restrict__ x4,
                                              float4* __restrict__ o4) {
    const int pbg = 4096 * DIM / 4;              // 524288 float4 per batch
    int i = blockIdx.x * 256 + threadIdx.x;      // 0..2097151
    int b = i / pbg;
    int off = i - b * pbg;
    int idx = b * (N_TOK * DIM / 4) + (DIM / 4) + off;   // skip cls token
    __stcs(&o4[idx], __ldcs(&x4[idx]));
}

// ============ K1: q = cls @ q_w.T (+ prefetch in_proj_w for K2) =============
// 256 blocks x 8 warps x 1 output = 2048 outputs.
__global__ void __launch_bounds__(256) k_q(const float* __restrict__ x,
                                           const float* __restrict__ q_w,
                                           const float* __restrict__ in_proj_w) {
    int t = threadIdx.x, wi = t >> 5, lane = t & 31;
    int tid = blockIdx.x * 256 + t;              // 0..65535
    if (tid < 32768) pf_l2(in_proj_w + (size_t)tid * 32);    // 4MB -> L2
    int o = blockIdx.x * 8 + wi;                 // 0..2047
    int b = o / DIM, r = o % DIM;
    float s = warp_dot<DIM / 4>((const float4*)(x + (size_t)b * N_TOK * DIM),
                                (const float4*)(q_w + (size_t)r * DIM));
    if (lane == 0) g_q[b * DIM + r] = s;
}

// ============ K2: xz = q @ in_proj_w.T ; conv-tap + silu ====================
// 1024 blocks x 8 warps x 1 output = 8192 outputs.
__global__ void __launch_bounds__(256) k_xz(const float* __restrict__ in_proj_w,
                                            const float* __restrict__ conv_w,
                                            const float* __restrict__ conv_b,
                                            const float* __restrict__ x_proj_w,
                                            const float* __restrict__ dt_w,
                                            const float* __restrict__ out_proj_w) {
    int t = threadIdx.x, wi = t >> 5, lane = t & 31;
    int tid = blockIdx.x * 256 + t;              // 0..262143
    // prefetch what K3/K4 need next: out_proj (16384 lines), x_proj (2048), dt_w (1024)
    if (tid < 16384)       pf_l2(out_proj_w + (size_t)tid * 32);
    else if (tid < 18432)  pf_l2(x_proj_w + (size_t)(tid - 16384) * 32);
    else if (tid < 19456)  pf_l2(dt_w + (size_t)(tid - 18432) * 32);

    int o = blockIdx.x * 8 + wi;                 // 0..8191
    int b = o / (2 * D_INNER), j = o % (2 * D_INNER);
    float s = warp_dot<DIM / 4>((const float4*)(g_q + b * DIM),
                                (const float4*)(in_proj_w + (size_t)j * DIM));
    if (lane == 0) {
        if (j < D_INNER) {
            // causal conv at t=0: only last tap contributes
            float v = s * conv_w[j * 4 + 3] + conv_b[j];
            g_xs[b * D_INNER + j] = siluf(v);
        } else {
            g_sz[b * D_INNER + (j - D_INNER)] = siluf(s);
        }
    }
}

// ============ K3: x_dbl + delta + first-step scan + gate (1 block/batch) ====
__global__ void __launch_bounds__(1024) k_scan(const float* __restrict__ x_proj_w,
                                               const float* __restrict__ dt_w,
                                               const float* __restrict__ dt_b,
                                               const float* __restrict__ Dv,
                                               const float* __restrict__ proj_w) {
    __shared__ __align__(16) float s_xs[D_INNER];
    __shared__ float s_db[DT_RANK + 2 * D_STATE];    // 64
    int b = blockIdx.x, t = threadIdx.x;
    int lane = t & 31, w = t >> 5;
    // prefetch proj_w (8192 lines) for K5 while we compute
    int gid = blockIdx.x * 1024 + t;             // 0..4095
    pf_l2(proj_w + (size_t)(2 * gid) * 32);
    pf_l2(proj_w + (size_t)(2 * gid + 1) * 32);

    s_xs[t] = g_xs[b * D_INNER + t];
    __syncthreads();

    // 64 rows of x_proj: 32 warps x 2 rows (coalesced float4 reads)
#pragma unroll
    for (int rr = 0; rr < 2; rr++) {
        int r = w * 2 + rr;
        float s = warp_dot<D_INNER / 4>((const float4*)s_xs,
                                        (const float4*)(x_proj_w + (size_t)r * D_INNER));
        if (lane == 0) s_db[r] = s;
    }
    __syncthreads();

    // delta pre-act: warp w handles rows [w*32, w*32+32), coalesced row loads
    float coef = s_db[lane];   // dt coefficient k = lane (DT_RANK == 32)
    float dtv = 0.0f;
#pragma unroll
    for (int rr = 0; rr < 32; rr++) {
        int r = w * 32 + rr;
        float v = dt_w[r * DT_RANK + lane] * coef;
#pragma unroll
        for (int off = 16; off; off >>= 1)
            v += __shfl_xor_sync(0xffffffffu, v, off);
        if (lane == rr) dtv = v;   // thread t = w*32+rr owns row t
    }
    float delta = softplusf(dtv + dt_b[t]);

    float bc = 0.0f;
#pragma unroll
    for (int n = 0; n < D_STATE; n++)
        bc += s_db[DT_RANK + n] * s_db[DT_RANK + D_STATE + n];

    float u = s_xs[t];
    // h0 = 0 => y = delta*u*(B.C) + u*D, gated by silu(z)
    g_y[b * D_INNER + t] = (delta * u * bc + u * Dv[t]) * g_sz[b * D_INNER + t];
}

// ============ K4: mixed = y @ out_proj_w.T ==================================
// 256 blocks x 8 warps x 1 output = 2048 outputs.
__global__ void __launch_bounds__(256) k_mixed(const float* __restrict__ out_proj_w) {
    int t = threadIdx.x, wi = t >> 5, lane = t & 31;
    int o = blockIdx.x * 8 + wi;
    int b = o / DIM, r = o % DIM;
    float s = warp_dot<D_INNER / 4>((const float4*)(g_y + b * D_INNER),
                                    (const float4*)(out_proj_w + (size_t)r * D_INNER));
    if (lane == 0) g_mixed[b * DIM + r] = s;
}

// ============ K5: upd_cls = mixed @ proj_w.T + proj_b -> out[:,0,:] =========
// 256 blocks x 8 warps x 1 output = 2048 outputs.
__global__ void __launch_bounds__(256) k_out(const float* __restrict__ proj_w,
                                             const float* __restrict__ proj_b,
                                             float* __restrict__ out) {
    int t = threadIdx.x, wi = t >> 5, lane = t & 31;
    int o = blockIdx.x * 8 + wi;
    int b = o / DIM, r = o % DIM;
    float s = warp_dot<DIM / 4>((const float4*)(g_mixed + b * DIM),
                                (const float4*)(proj_w + (size_t)r * DIM));
    if (lane == 0)
        out[(size_t)b * N_TOK * DIM + r] = s + proj_b[r];
}

// ---------------- launch: fork with HIGH-PRIORITY chain stream --------------
extern "C" void kernel_launch(void* const* d_in, const int* in_sizes, int n_in,
                              void* d_out, int out_size) {
    const float* x         = (const float*)d_in[0];
    const float* q_w       = (const float*)d_in[1];
    const float* in_proj_w = (const float*)d_in[2];
    const float* conv_w    = (const float*)d_in[3];
    const float* conv_b    = (const float*)d_in[4];
    const float* x_proj_w  = (const float*)d_in[5];
    const float* dt_w      = (const float*)d_in[6];
    const float* dt_b      = (const float*)d_in[7];
    // d_in[8] = A_log (unused: h0 = 0 at the single contributing scan step)
    const float* Dv        = (const float*)d_in[9];
    const float* out_proj_w= (const float*)d_in[10];
    const float* proj_w    = (const float*)d_in[11];
    const float* proj_b    = (const float*)d_in[12];
    float* out = (float*)d_out;

    // One-time host-resource creation (streams/events only, no device memory).
    static cudaStream_t s1 = nullptr;
    static cudaEvent_t  e0 = nullptr, e1 = nullptr;
    static bool tried = false;
    if (!tried) {
        tried = true;
        int lo = 0, hi = 0;
        cudaDeviceGetStreamPriorityRange(&lo, &hi);   // hi = highest priority
        if (cudaStreamCreateWithPriority(&s1, cudaStreamNonBlocking, hi)
                != cudaSuccess)
            s1 = nullptr;
        if (s1 && (cudaEventCreateWithFlags(&e0, cudaEventDisableTiming) != cudaSuccess ||
                   cudaEventCreateWithFlags(&e1, cudaEventDisableTiming) != cudaSuccess)) {
            s1 = nullptr; e0 = nullptr; e1 = nullptr;
        }
        cudaGetLastError();
    }

    if (s1 && e0 && e1) {
        // fork: high-priority chain branch runs during the copy; tiny copy
        // blocks retire constantly, letting chain blocks take their slots.
        cudaEventRecord(e0, 0);
        cudaStreamWaitEvent(s1, e0, 0);

        k_copy <<<8192, 256, 0, 0>>>((const float4*)x, (float4*)out);

        k_q    <<<256,  256, 0, s1>>>(x, q_w, in_proj_w);
        k_xz   <<<1024, 256, 0, s1>>>(in_proj_w, conv_w, conv_b,
                                      x_proj_w, dt_w, out_proj_w);
        k_scan <<<B_SZ, 1024, 0, s1>>>(x_proj_w, dt_w, dt_b, Dv, proj_w);
        k_mixed<<<256,  256, 0, s1>>>(out_proj_w);
        k_out  <<<256,  256, 0, s1>>>(proj_w, proj_b, out);

        // join back into the main stream
        cudaEventRecord(e1, s1);
        cudaStreamWaitEvent(0, e1, 0);
    } else {
        // serial fallback (identical math)
        k_copy <<<8192, 256>>>((const float4*)x, (float4*)out);
        k_q    <<<256,  256>>>(x, q_w, in_proj_w);
        k_xz   <<<1024, 256>>>(in_proj_w, conv_w, conv_b,
                               x_proj_w, dt_w, out_proj_w);
        k_scan <<<B_SZ, 1024>>>(x_proj_w, dt_w, dt_b, Dv, proj_w);
        k_mixed<<<256,  256>>>(out_proj_w);
        k_out  <<<256,  256>>>(proj_w, proj_b, out);
    }
}

// round 17
// speedup vs baseline: 1.0472x; 1.0472x over previous
#include <cuda_runtime.h>

#define DIM     512
#define D_INNER 1024
#define DT_RANK 32
#define D_STATE 16
#define B_SZ    4
#define N_TOK   4097

// ---------------- scratch (device globals, allocation-free) ----------------
__device__ __align__(16) float g_q    [B_SZ * DIM];
__device__ __align__(16) float g_xs   [B_SZ * D_INNER];
__device__ __align__(16) float g_sz   [B_SZ * D_INNER];
__device__ __align__(16) float g_y    [B_SZ * D_INNER];
__device__ __align__(16) float g_mixed[B_SZ * DIM];

// ---------------- helpers ----------------
__device__ __forceinline__ float siluf(float x) { return x / (1.0f + __expf(-x)); }
__device__ __forceinline__ float softplusf(float x) {
    return (x > 20.0f) ? x : log1pf(__expf(x));
}
__device__ __forceinline__ void pf_l2(const float* p) {
    asm volatile("prefetch.global.L2 [%0];" :: "l"(p));
}

// Warp-collective dot of two length-(N4*4) float vectors (float4 reads).
template <int N4>
__device__ __forceinline__ float warp_dot(const float4* __restrict__ v4,
                                          const float4* __restrict__ w4) {
    int lane = threadIdx.x & 31;
    float s = 0.0f;
#pragma unroll
    for (int i = 0; i < N4 / 32; i++) {
        float4 a = v4[lane + i * 32];
        float4 b = w4[lane + i * 32];
        s += a.x * b.x + a.y * b.y + a.z * b.z + a.w * b.w;
    }
#pragma unroll
    for (int off = 16; off; off >>= 1)
        s += __shfl_xor_sync(0xffffffffu, s, off);
    return s;
}

// ============ NODE 1: q matvec + bulk patch copy (R14-proven) ===============
// Blocks [0,256): q = cls @ q_w.T (2048 warps, 1 row each) + in_proj prefetch.
// Blocks [256, 256+2048): streaming copy (R7-proven config).
#define Q_BLOCKS    256
#define COPY_BLOCKS 2048
__global__ void __launch_bounds__(256)
k_copy_q(const float* __restrict__ x,
         const float* __restrict__ q_w,
         const float* __restrict__ in_proj_w,
         float* __restrict__ out) {
    int t = threadIdx.x;
    if (blockIdx.x < Q_BLOCKS) {
        int tid = blockIdx.x * 256 + t;              // 0..65535
        if (tid < 32768) pf_l2(in_proj_w + (size_t)tid * 32);    // 4MB -> L2
        int gw = blockIdx.x * 8 + (t >> 5);          // 0..2047
        int b = gw / DIM, r = gw % DIM;
        float s = warp_dot<DIM / 4>((const float4*)(x + (size_t)b * N_TOK * DIM),
                                    (const float4*)(q_w + (size_t)r * DIM));
        if ((t & 31) == 0) g_q[b * DIM + r] = s;
        return;
    }
    const float4* x4 = (const float4*)x;
    float4* o4 = (float4*)out;
    const int pbg = 4096 * DIM / 4;                  // 524288 float4 per batch
    int tid = (blockIdx.x - Q_BLOCKS) * 256 + t;     // 0..524287
#pragma unroll
    for (int k = 0; k < 4; k++) {
        int i = tid + k * 524288;
        int b = i / pbg;
        int off = i - b * pbg;
        int idx = b * (N_TOK * DIM / 4) + (DIM / 4) + off;   // skip cls token
        __stcs(&o4[idx], __ldcs(&x4[idx]));
    }
}

// ============ NODE 2: xz = q @ in_proj_w.T ; conv-tap + silu ================
// 1024 blocks x 8 warps x 1 output = 8192 outputs.
__global__ void __launch_bounds__(256) k_xz(const float* __restrict__ in_proj_w,
                                            const float* __restrict__ conv_w,
                                            const float* __restrict__ conv_b,
                                            const float* __restrict__ x_proj_w,
                                            const float* __restrict__ dt_w,
                                            const float* __restrict__ out_proj_w) {
    int t = threadIdx.x, wi = t >> 5, lane = t & 31;
    int tid = blockIdx.x * 256 + t;              // 0..262143
    // prefetch what later nodes need: out_proj (16384 lines), x_proj (2048), dt_w (1024)
    if (tid < 16384)       pf_l2(out_proj_w + (size_t)tid * 32);
    else if (tid < 18432)  pf_l2(x_proj_w + (size_t)(tid - 16384) * 32);
    else if (tid < 19456)  pf_l2(dt_w + (size_t)(tid - 18432) * 32);

    int o = blockIdx.x * 8 + wi;                 // 0..8191
    int b = o / (2 * D_INNER), j = o % (2 * D_INNER);
    float s = warp_dot<DIM / 4>((const float4*)(g_q + b * DIM),
                                (const float4*)(in_proj_w + (size_t)j * DIM));
    if (lane == 0) {
        if (j < D_INNER) {
            // causal conv at t=0: only last tap contributes
            float v = s * conv_w[j * 4 + 3] + conv_b[j];
            g_xs[b * D_INNER + j] = siluf(v);
        } else {
            g_sz[b * D_INNER + (j - D_INNER)] = siluf(s);
        }
    }
}

// ============ NODE 3: x_dbl + delta + first-step scan + gate (1 blk/batch) ==
__global__ void __launch_bounds__(1024) k_scan(const float* __restrict__ x_proj_w,
                                               const float* __restrict__ dt_w,
                                               const float* __restrict__ dt_b,
                                               const float* __restrict__ Dv,
                                               const float* __restrict__ proj_w) {
    __shared__ __align__(16) float s_xs[D_INNER];
    __shared__ float s_db[DT_RANK + 2 * D_STATE];    // 64
    int b = blockIdx.x, t = threadIdx.x;
    int lane = t & 31, w = t >> 5;
    // prefetch proj_w (8192 lines) for the final node
    int gid = blockIdx.x * 1024 + t;             // 0..4095
    pf_l2(proj_w + (size_t)(2 * gid) * 32);
    pf_l2(proj_w + (size_t)(2 * gid + 1) * 32);

    s_xs[t] = g_xs[b * D_INNER + t];
    __syncthreads();

    // 64 rows of x_proj: 32 warps x 2 rows (coalesced float4 reads)
#pragma unroll
    for (int rr = 0; rr < 2; rr++) {
        int r = w * 2 + rr;
        float s = warp_dot<D_INNER / 4>((const float4*)s_xs,
                                        (const float4*)(x_proj_w + (size_t)r * D_INNER));
        if (lane == 0) s_db[r] = s;
    }
    __syncthreads();

    // delta pre-act: warp w handles rows [w*32, w*32+32), coalesced row loads
    float coef = s_db[lane];   // dt coefficient k = lane (DT_RANK == 32)
    float dtv = 0.0f;
#pragma unroll
    for (int rr = 0; rr < 32; rr++) {
        int r = w * 32 + rr;
        float v = dt_w[r * DT_RANK + lane] * coef;
#pragma unroll
        for (int off = 16; off; off >>= 1)
            v += __shfl_xor_sync(0xffffffffu, v, off);
        if (lane == rr) dtv = v;   // thread t = w*32+rr owns row t
    }
    float delta = softplusf(dtv + dt_b[t]);

    float bc = 0.0f;
#pragma unroll
    for (int n = 0; n < D_STATE; n++)
        bc += s_db[DT_RANK + n] * s_db[DT_RANK + D_STATE + n];

    float u = s_xs[t];
    // h0 = 0 => y = delta*u*(B.C) + u*D, gated by silu(z)
    g_y[b * D_INNER + t] = (delta * u * bc + u * Dv[t]) * g_sz[b * D_INNER + t];
}

// ============ NODE 4: mixed = y @ out_proj_w.T ==============================
// 256 blocks x 8 warps x 1 output = 2048 outputs.
__global__ void __launch_bounds__(256) k_mixed(const float* __restrict__ out_proj_w) {
    int t = threadIdx.x, wi = t >> 5, lane = t & 31;
    int o = blockIdx.x * 8 + wi;
    int b = o / DIM, r = o % DIM;
    float s = warp_dot<D_INNER / 4>((const float4*)(g_y + b * D_INNER),
                                    (const float4*)(out_proj_w + (size_t)r * D_INNER));
    if (lane == 0) g_mixed[b * DIM + r] = s;
}

// ============ NODE 5: upd_cls = mixed @ proj_w.T + proj_b -> out[:,0,:] =====
// 256 blocks x 8 warps x 1 output = 2048 outputs.
__global__ void __launch_bounds__(256) k_out(const float* __restrict__ proj_w,
                                             const float* __restrict__ proj_b,
                                             float* __restrict__ out) {
    int t = threadIdx.x, wi = t >> 5, lane = t & 31;
    int o = blockIdx.x * 8 + wi;
    int b = o / DIM, r = o % DIM;
    float s = warp_dot<DIM / 4>((const float4*)(g_mixed + b * DIM),
                                (const float4*)(proj_w + (size_t)r * DIM));
    if (lane == 0)
        out[(size_t)b * N_TOK * DIM + r] = s + proj_b[r];
}

// ---------------- launch: 5 nodes, ONE stream, ZERO event nodes ------------
extern "C" void kernel_launch(void* const* d_in, const int* in_sizes, int n_in,
                              void* d_out, int out_size) {
    const float* x         = (const float*)d_in[0];
    const float* q_w       = (const float*)d_in[1];
    const float* in_proj_w = (const float*)d_in[2];
    const float* conv_w    = (const float*)d_in[3];
    const float* conv_b    = (const float*)d_in[4];
    const float* x_proj_w  = (const float*)d_in[5];
    const float* dt_w      = (const float*)d_in[6];
    const float* dt_b      = (const float*)d_in[7];
    // d_in[8] = A_log (unused: h0 = 0 at the single contributing scan step)
    const float* Dv        = (const float*)d_in[9];
    const float* out_proj_w= (const float*)d_in[10];
    const float* proj_w    = (const float*)d_in[11];
    const float* proj_b    = (const float*)d_in[12];
    float* out = (float*)d_out;

    k_copy_q<<<Q_BLOCKS + COPY_BLOCKS, 256>>>(x, q_w, in_proj_w, out);
    k_xz    <<<1024, 256>>>(in_proj_w, conv_w, conv_b,
                            x_proj_w, dt_w, out_proj_w);
    k_scan  <<<B_SZ, 1024>>>(x_proj_w, dt_w, dt_b, Dv, proj_w);
    k_mixed <<<256,  256>>>(out_proj_w);
    k_out   <<<256,  256>>>(proj_w, proj_b, out);
}